// round 6
// baseline (speedup 1.0000x reference)
#include <cuda_runtime.h>
#include <math.h>

#define H    64
#define G    192      // 3*H
#define HIDD 128
#define APP  512
#define TSTEPS 16
#define TPB_A 192
#define TPB_B 512

typedef unsigned long long ull;

// ---- device scratch (folded matrices) ----
__device__ __align__(16) float g_M1[HIDD * APP];   // Wf[:, :128] @ Wa   [128,512]
__device__ __align__(16) float g_M2[HIDD * H];     // Wf[:, 128:] @ Wt   [128,64]
__device__ __align__(16) float g_c [HIDD];         // Wf_L@ba + Wf_R@bt + bf

// ---- packed f32x2 helpers (Blackwell FFMA2) ----
__device__ __forceinline__ void fma2(ull& d, ull a, ull b) {
    asm("fma.rn.f32x2 %0, %1, %2, %0;" : "+l"(d) : "l"(a), "l"(b));
}
__device__ __forceinline__ float hsum2(ull a) {
    float lo, hi;
    asm("mov.b64 {%0, %1}, %2;" : "=f"(lo), "=f"(hi) : "l"(a));
    return lo + hi;
}
__device__ __forceinline__ float sigmoid_f(float x) {
    return __fdividef(1.f, 1.f + __expf(-x));
}
__device__ __forceinline__ float tanh_f(float x) {
    return __fdividef(2.f, 1.f + __expf(-2.f * x)) - 1.f;
}

// ============================================================
// Kernel C: fold projection matrices (runs once per launch)
// ============================================================
__global__ void precompute_kernel(const float* __restrict__ Wt, const float* __restrict__ bt,
                                  const float* __restrict__ Wa, const float* __restrict__ ba,
                                  const float* __restrict__ Wf, const float* __restrict__ bf) {
    int o = blockIdx.x;            // 0..127
    int t = threadIdx.x;           // 0..255
    const float* wfo = Wf + o * (2 * HIDD);
    // M1[o][k] = sum_c Wf[o][c] * Wa[c][k]
    for (int k = t; k < APP; k += 256) {
        float acc = 0.f;
        for (int c = 0; c < HIDD; ++c)
            acc = fmaf(wfo[c], Wa[(size_t)c * APP + k], acc);
        g_M1[(size_t)o * APP + k] = acc;
    }
    // M2[o][k] = sum_c Wf[o][128+c] * Wt[c][k]
    if (t < H) {
        float acc = 0.f;
        for (int c = 0; c < HIDD; ++c)
            acc = fmaf(wfo[HIDD + c], Wt[c * H + t], acc);
        g_M2[o * H + t] = acc;
    }
    // c[o]
    if (t == 0) {
        float acc = bf[o];
        for (int c = 0; c < HIDD; ++c) acc = fmaf(wfo[c], ba[c], acc);
        for (int c = 0; c < HIDD; ++c) acc = fmaf(wfo[HIDD + c], bt[c], acc);
        g_c[o] = acc;
    }
}

// ============================================================
// Kernel A: GRU (thread-per-row) + (M2 @ h_last + c) -> out partial
// Dyn smem layout:
//   [0, 49152)      W_hh as ulonglong2[192*16]  (reused as M2 after GRU)
//   [49152, 98304)  h buffer ull[32 * 192]  ([k2][tid])
//   [98304, ...)    Wih0[192], Wih1[192], bih[192], bhh[192], c[128]
// ============================================================
#define SMEM_A (49152 + 49152 + 4*192*4 + 128*4)

__global__ __launch_bounds__(TPB_A, 2)
void gru_kernel(const float* __restrict__ centroid,
                const float* __restrict__ W_ih, const float* __restrict__ W_hh,
                const float* __restrict__ b_ih, const float* __restrict__ b_hh,
                float* __restrict__ out, int B) {
    extern __shared__ char sm[];
    ulonglong2* sW   = (ulonglong2*)sm;                 // 3072 entries
    ull*        sH   = (ull*)(sm + 49152);              // 32*192
    float*      sHf  = (float*)sH;
    float*      sW0  = (float*)(sm + 98304);
    float*      sW1  = sW0 + G;
    float*      sBi  = sW1 + G;
    float*      sBh  = sBi + G;
    float*      sC   = sBh + G;

    int tid = threadIdx.x;
    long long row = (long long)blockIdx.x * TPB_A + tid;
    bool valid = (row < (long long)B);

    // stage W_hh (12288 floats = 3072 x 16B)
    {
        const ulonglong2* gW = (const ulonglong2*)W_hh;
        for (int i = tid; i < 3072; i += TPB_A) sW[i] = gW[i];
        for (int i = tid; i < G; i += TPB_A) {
            sW0[i] = W_ih[2 * i];
            sW1[i] = W_ih[2 * i + 1];
            sBi[i] = b_ih[i];
            sBh[i] = b_hh[i];
        }
    }

    ull h2[32];
    #pragma unroll
    for (int k = 0; k < 32; ++k) { h2[k] = 0ULL; sH[k * TPB_A + tid] = 0ULL; }
    __syncthreads();

    const float2* xrow = (const float2*)centroid + (valid ? row * TSTEPS : 0);

    #pragma unroll 1
    for (int t = 0; t < TSTEPS; ++t) {
        float2 xt = valid ? xrow[t] : make_float2(0.f, 0.f);
        float x0 = xt.x, x1 = xt.y;

        #pragma unroll 1
        for (int j = 0; j < H; ++j) {
            int jr = j, jz = H + j, jn = 2 * H + j;

            ull a0 = 0, a1 = 0;
            const ulonglong2* wr = sW + jr * 16;
            #pragma unroll
            for (int k = 0; k < 16; ++k) {
                ulonglong2 w = wr[k];
                fma2(a0, w.x, h2[2 * k]); fma2(a1, w.y, h2[2 * k + 1]);
            }
            float hr = hsum2(a0) + hsum2(a1) + sBh[jr];
            float xr = fmaf(sW0[jr], x0, fmaf(sW1[jr], x1, sBi[jr]));
            float r  = sigmoid_f(xr + hr);

            ull b0 = 0, b1 = 0;
            const ulonglong2* wz = sW + jz * 16;
            #pragma unroll
            for (int k = 0; k < 16; ++k) {
                ulonglong2 w = wz[k];
                fma2(b0, w.x, h2[2 * k]); fma2(b1, w.y, h2[2 * k + 1]);
            }
            float hz = hsum2(b0) + hsum2(b1) + sBh[jz];
            float xz = fmaf(sW0[jz], x0, fmaf(sW1[jz], x1, sBi[jz]));
            float z  = sigmoid_f(xz + hz);

            ull c0 = 0, c1 = 0;
            const ulonglong2* wn = sW + jn * 16;
            #pragma unroll
            for (int k = 0; k < 16; ++k) {
                ulonglong2 w = wn[k];
                fma2(c0, w.x, h2[2 * k]); fma2(c1, w.y, h2[2 * k + 1]);
            }
            float hn = hsum2(c0) + hsum2(c1) + sBh[jn];
            float xn = fmaf(sW0[jn], x0, fmaf(sW1[jn], x1, sBi[jn]));
            float n  = tanh_f(fmaf(r, hn, xn));

            // h_new[j] = n + z*(h[j]-n); h[j] lives in this thread's private smem column
            int fidx = (j >> 1) * (2 * TPB_A) + 2 * tid + (j & 1);
            float hj = sHf[fidx];
            sHf[fidx] = n + z * (hj - n);
        }
        // refresh register copy of h from smem
        #pragma unroll
        for (int k = 0; k < 32; ++k) h2[k] = sH[k * TPB_A + tid];
    }

    // ---- epilogue: out_partial = M2 @ h_last + c ----
    __syncthreads();
    {
        const ulonglong2* gM2 = (const ulonglong2*)g_M2;
        for (int i = tid; i < HIDD * H / 4; i += TPB_A) sW[i] = gM2[i];  // 2048 x 16B
        for (int i = tid; i < HIDD; i += TPB_A) sC[i] = g_c[i];
    }
    __syncthreads();

    if (valid) {
        float* orow = out + row * HIDD;
        #pragma unroll 1
        for (int ob = 0; ob < HIDD; ob += 4) {
            ull a0=0,a1=0,b0=0,b1=0,c0=0,c1=0,d0=0,d1=0;
            const ulonglong2* w0 = sW + (ob + 0) * 16;
            const ulonglong2* w1 = sW + (ob + 1) * 16;
            const ulonglong2* w2 = sW + (ob + 2) * 16;
            const ulonglong2* w3 = sW + (ob + 3) * 16;
            #pragma unroll
            for (int k = 0; k < 16; ++k) {
                ulonglong2 q0 = w0[k], q1 = w1[k], q2 = w2[k], q3 = w3[k];
                fma2(a0, q0.x, h2[2*k]); fma2(a1, q0.y, h2[2*k+1]);
                fma2(b0, q1.x, h2[2*k]); fma2(b1, q1.y, h2[2*k+1]);
                fma2(c0, q2.x, h2[2*k]); fma2(c1, q2.y, h2[2*k+1]);
                fma2(d0, q3.x, h2[2*k]); fma2(d1, q3.y, h2[2*k+1]);
            }
            float4 v;
            v.x = hsum2(a0) + hsum2(a1) + sC[ob + 0];
            v.y = hsum2(b0) + hsum2(b1) + sC[ob + 1];
            v.z = hsum2(c0) + hsum2(c1) + sC[ob + 2];
            v.w = hsum2(d0) + hsum2(d1) + sC[ob + 3];
            *(float4*)(orow + ob) = v;
        }
    }
}

// ============================================================
// Kernel B: out = gelu(out_partial + M1 @ appearance)
// CTA: 128 rows x 128 outs, 512 threads, 8x4 f32x2 microtiles
// ============================================================
__global__ __launch_bounds__(TPB_B, 1)
void proj_kernel(const float* __restrict__ app, float* __restrict__ out, int B) {
    __shared__ ull sa[16 * HIDD];   // [k2][row]
    __shared__ ull sw[16 * HIDD];   // [k2][o]

    int tid = threadIdx.x;
    long long row0 = (long long)blockIdx.x * HIDD;
    int lr = tid & 127;       // loader row / loader out
    int kg = tid >> 7;        // 0..3 (k-group of 8 floats)
    int rb = tid & 15;        // compute: row base
    int og = tid >> 4;        // compute: out base (0..31)

    ull acc[8][4];
    #pragma unroll
    for (int i = 0; i < 8; ++i)
        #pragma unroll
        for (int j = 0; j < 4; ++j) acc[i][j] = 0ULL;

    long long ar = row0 + lr;
    bool aval = (ar < (long long)B);
    const ulonglong2* aptr = (const ulonglong2*)(app + (aval ? ar : 0) * APP);
    const ulonglong2* wptr = (const ulonglong2*)(g_M1 + (size_t)lr * APP);

    #pragma unroll 1
    for (int kt = 0; kt < APP; kt += 32) {
        int kof = kt + kg * 8;            // float offset, multiple of 8
        ulonglong2 zz; zz.x = 0ULL; zz.y = 0ULL;
        ulonglong2 va0 = zz, va1 = zz;
        if (aval) { va0 = aptr[kof / 4]; va1 = aptr[kof / 4 + 1]; }
        ulonglong2 vw0 = wptr[kof / 4], vw1 = wptr[kof / 4 + 1];
        int k2b = kg * 4;
        sa[(k2b + 0) * HIDD + lr] = va0.x;
        sa[(k2b + 1) * HIDD + lr] = va0.y;
        sa[(k2b + 2) * HIDD + lr] = va1.x;
        sa[(k2b + 3) * HIDD + lr] = va1.y;
        sw[(k2b + 0) * HIDD + lr] = vw0.x;
        sw[(k2b + 1) * HIDD + lr] = vw0.y;
        sw[(k2b + 2) * HIDD + lr] = vw1.x;
        sw[(k2b + 3) * HIDD + lr] = vw1.y;
        __syncthreads();

        #pragma unroll
        for (int k2 = 0; k2 < 16; ++k2) {
            ull a2[8], w2[4];
            #pragma unroll
            for (int i = 0; i < 8; ++i) a2[i] = sa[k2 * HIDD + rb + 16 * i];
            #pragma unroll
            for (int j = 0; j < 4; ++j) w2[j] = sw[k2 * HIDD + og + 32 * j];
            #pragma unroll
            for (int i = 0; i < 8; ++i)
                #pragma unroll
                for (int j = 0; j < 4; ++j) fma2(acc[i][j], a2[i], w2[j]);
        }
        __syncthreads();
    }

    #pragma unroll
    for (int i = 0; i < 8; ++i) {
        long long r = row0 + rb + 16 * i;
        if (r < (long long)B) {
            #pragma unroll
            for (int j = 0; j < 4; ++j) {
                int o = og + 32 * j;
                long long idx = r * HIDD + o;
                float v = hsum2(acc[i][j]) + out[idx];
                out[idx] = 0.5f * v * (1.f + erff(v * 0.7071067811865476f));
            }
        }
    }
}

// ============================================================
extern "C" void kernel_launch(void* const* d_in, const int* in_sizes, int n_in,
                              void* d_out, int out_size) {
    const float* app  = (const float*)d_in[0];
    const float* cen  = (const float*)d_in[1];
    const float* W_ih = (const float*)d_in[2];
    const float* W_hh = (const float*)d_in[3];
    const float* b_ih = (const float*)d_in[4];
    const float* b_hh = (const float*)d_in[5];
    const float* Wt   = (const float*)d_in[6];
    const float* bt   = (const float*)d_in[7];
    const float* Wa   = (const float*)d_in[8];
    const float* ba   = (const float*)d_in[9];
    const float* Wf   = (const float*)d_in[10];
    const float* bf   = (const float*)d_in[11];
    float* out = (float*)d_out;

    int B = in_sizes[0] / APP;

    // Drain any sticky prior error; non-stream call, capture-legal, no timing effect.
    (void)cudaGetLastError();
    // Non-stream API: legal during capture, idempotent. Ignore return.
    (void)cudaFuncSetAttribute(gru_kernel,
                               cudaFuncAttributeMaxDynamicSharedMemorySize, SMEM_A);

    precompute_kernel<<<HIDD, 256>>>(Wt, bt, Wa, ba, Wf, bf);

    int gridA = (B + TPB_A - 1) / TPB_A;
    gru_kernel<<<gridA, TPB_A, SMEM_A>>>(cen, W_ih, W_hh, b_ih, b_hh, out, B);

    int gridB = (B + HIDD - 1) / HIDD;
    proj_kernel<<<gridB, TPB_B>>>(app, out, B);
}